// round 5
// baseline (speedup 1.0000x reference)
#include <cuda_runtime.h>
#include <cuda_fp16.h>
#include <cstdint>
#include <math.h>

#define BB   64
#define CIN  256
#define HID  256
#define TT   512
#define G4   1024   // 4*HID

// ---------------- scratch (__device__ globals) ------------------------------
__device__ float g_wx[(size_t)TT * BB * G4];      // [t][b][col]  128 MiB
// Recurrence weights fp16: per (b,half): 16 chunks x 512 cols x uint4(8 halves)
__device__ uint4 g_wA[(size_t)BB * 2 * 16 * 512]; // own-k block  (registers)
__device__ uint4 g_wB[(size_t)BB * 2 * 16 * 512]; // peer-k block (SMEM)

// local col lc in [0,512) -> global gate column
__device__ __forceinline__ int gcol(int lc, int half) {
    int g = ((lc >> 7) & 1) | ((lc >> 8) << 1);
    return g * 256 + half * 128 + (lc & 127);
}

// fast activations (MUFU.EX2/RCP based, ~1e-6 rel err)
__device__ __forceinline__ float tanh_f(float x) {
    float e = __expf(2.0f * x);
    return 1.0f - __fdividef(2.0f, e + 1.0f);
}
__device__ __forceinline__ float sig_f(float x) {
    return __fdividef(1.0f, 1.0f + __expf(-x));
}

// ---------------- conv: W_hh fp32 -> fp16 blobs (proven) --------------------
__global__ __launch_bounds__(256) void conv_whh_kernel(const float* __restrict__ Whh) {
    int t    = blockIdx.x * 256 + threadIdx.x;
    int lc   = t & 511;
    int k8   = (t >> 9) & 15;
    int half = (t >> 13) & 1;
    int b    = t >> 14;
    int col  = gcol(lc, half);
    {
        int kg0 = half * 128 + k8 * 8;
        const float* s = Whh + ((size_t)b * HID + kg0) * G4 + col;
        __half hx[8];
        #pragma unroll
        for (int i = 0; i < 8; i++) hx[i] = __float2half(s[(size_t)i * G4]);
        g_wA[t] = *(uint4*)hx;
    }
    {
        int kg0 = (1 - half) * 128 + k8 * 8;
        const float* s = Whh + ((size_t)b * HID + kg0) * G4 + col;
        __half hx[8];
        #pragma unroll
        for (int i = 0; i < 8; i++) hx[i] = __float2half(s[(size_t)i * G4]);
        g_wB[t] = *(uint4*)hx;
    }
}

// ---------------- phase 1: fp32 GEMM with packed FFMA2 ----------------------
// g_wx[t][b][col] = sum_k x[b][k][t] * W_ih[b][k][col] + b_h[b][col]
__global__ __launch_bounds__(256) void wx_gemm_kernel(
    const float* __restrict__ x,     // [B][CIN][T]
    const float* __restrict__ Wih,   // [B][CIN][4H]
    const float* __restrict__ bh)    // [B][1][4H]
{
    __shared__ float As[32][64];   // [k][m]
    __shared__ float Bs[32][64];   // [k][n]

    const int bt  = blockIdx.x;
    const int bn  = blockIdx.y;
    const int b   = blockIdx.z;
    const int tid = threadIdx.x;
    const int tm0 = (tid & 15) * 4;
    const int tn0 = (tid >> 4) * 4;

    const float* xb = x   + (size_t)b * CIN * TT;
    const float* wb = Wih + (size_t)b * CIN * G4;

    unsigned long long acc2[4][2] = {};   // [m][n-pair], packed {f32,f32}

    for (int kb = 0; kb < CIN; kb += 32) {
        #pragma unroll
        for (int p = 0; p < 8; p++) {
            int e = tid + p * 256;
            int k = e >> 6, m = e & 63;
            As[k][m] = xb[(size_t)(kb + k) * TT + bt * 64 + m];
            Bs[k][m] = wb[(size_t)(kb + k) * G4 + bn * 64 + m];
        }
        __syncthreads();
        #pragma unroll
        for (int k = 0; k < 32; k++) {
            float4 av = *(const float4*)&As[k][tm0];
            unsigned long long c01 = *(const unsigned long long*)&Bs[k][tn0];
            unsigned long long c23 = *(const unsigned long long*)&Bs[k][tn0 + 2];
            float a4[4] = {av.x, av.y, av.z, av.w};
            #pragma unroll
            for (int i = 0; i < 4; i++) {
                unsigned long long aa;
                uint32_t au = __float_as_uint(a4[i]);
                asm("mov.b64 %0, {%1,%1};" : "=l"(aa) : "r"(au));
                asm("fma.rn.f32x2 %0, %1, %2, %0;"
                    : "+l"(acc2[i][0]) : "l"(aa), "l"(c01));
                asm("fma.rn.f32x2 %0, %1, %2, %0;"
                    : "+l"(acc2[i][1]) : "l"(aa), "l"(c23));
            }
        }
        __syncthreads();
    }

    const float* bb = bh + (size_t)b * G4 + bn * 64 + tn0;
    float4 bias = *(const float4*)bb;
    #pragma unroll
    for (int i = 0; i < 4; i++) {
        int t = bt * 64 + tm0 + i;
        float4 r;
        r.x = __uint_as_float((uint32_t)(acc2[i][0]      )) + bias.x;
        r.y = __uint_as_float((uint32_t)(acc2[i][0] >> 32)) + bias.y;
        r.z = __uint_as_float((uint32_t)(acc2[i][1]      )) + bias.z;
        r.w = __uint_as_float((uint32_t)(acc2[i][1] >> 32)) + bias.w;
        *(float4*)&g_wx[((size_t)t * BB + b) * G4 + bn * 64 + tn0] = r;
    }
}

// ---------------- phase 2: recurrence, 512 thr, 1 col/thread ---------------
#define SMEM_W_BYTES  (16 * 512 * 16)                 // 131072
#define SMEM_HS_OFF   SMEM_W_BYTES
#define SMEM_GS_OFF   (SMEM_HS_OFF + 2 * 128 * 4)
#define SMEM_TOTAL_R  (SMEM_GS_OFF + 512 * 4)         // 134144 B

__global__ void __cluster_dims__(2, 1, 1) __launch_bounds__(512, 1)
lstm_rec_kernel(const float* __restrict__ h0,
                const float* __restrict__ c0,
                float* __restrict__ out)
{
    extern __shared__ char smem[];
    uint4*   w_s  = (uint4*)smem;                     // peer-k weights 16x512
    __half2* hs2  = (__half2*)(smem + SMEM_HS_OFF);   // h state, 2 buffers
    float*   gsh  = (float*)(smem + SMEM_GS_OFF);     // gate exchange

    const int tid    = threadIdx.x;                   // 0..511 = local col
    const int b      = blockIdx.x >> 1;
    const int half   = blockIdx.x & 1;
    const int HALF16 = half * 16;
    const int PEER16 = 16 - HALF16;

    // --- one-time weight residency: 16 own-k chunks in regs, 16 peer in SMEM
    uint4 wregA[16];
    const uint4* gwa = g_wA + ((size_t)(b * 2 + half) << 13);  // *16*512
    #pragma unroll
    for (int a = 0; a < 16; a++) wregA[a] = gwa[a * 512 + tid];
    const uint4* gwb = g_wB + ((size_t)(b * 2 + half) << 13);
    #pragma unroll
    for (int i = 0; i < 16; i++) w_s[i * 512 + tid] = gwb[i * 512 + tid];

    // --- init state ---
    float c = 0.0f;
    if (tid < 128) {
        c = c0[b * HID + half * 128 + tid];
        hs2[tid] = __floats2half2_rn(h0[b * HID + 2 * tid],
                                     h0[b * HID + 2 * tid + 1]);
    }
    __syncthreads();
    asm volatile("barrier.cluster.arrive.aligned;\n\t"
                 "barrier.cluster.wait.aligned;" ::: "memory");

    const uint32_t hsAddrBase = (uint32_t)__cvta_generic_to_shared(hs2);
    const uint32_t peerRank   = (uint32_t)(half ^ 1);

    const int colA = gcol(tid, half);
    const float* wx_ptr = g_wx + (size_t)b * G4 + colA;

    float wx = __ldg(wx_ptr);
    const __half2 hz = __float2half2_rn(0.0f);

    #pragma unroll 1
    for (int t = 0; t < TT; t++) {
        const int p = t & 1;

        // prefetch next step's wx (hidden behind the whole step)
        float nx = wx;
        if (t + 1 < TT) nx = __ldg(wx_ptr + (size_t)(t + 1) * (BB * G4));

        float acc = wx;
        const __half2* hsp = hs2 + p * 128;

        // ---- phase A: own-k block (register weights, locally-produced h) ----
        #pragma unroll
        for (int q = 0; q < 4; q++) {
            __half2 s = hz;
            #pragma unroll
            for (int i = 0; i < 4; i++) {
                int a  = q * 4 + i;
                int k8 = HALF16 + a;
                uint4 hv = *(const uint4*)(hsp + k8 * 4);
                uint4 wa = wregA[a];
                s = __hfma2(*(__half2*)&hv.x, *(__half2*)&wa.x, s);
                s = __hfma2(*(__half2*)&hv.y, *(__half2*)&wa.y, s);
                s = __hfma2(*(__half2*)&hv.z, *(__half2*)&wa.z, s);
                s = __hfma2(*(__half2*)&hv.w, *(__half2*)&wa.w, s);
            }
            float2 f = __half22float2(s);
            acc += f.x + f.y;
        }

        // wait for peer's h of this step (arrive was at end of previous step)
        if (t) asm volatile("barrier.cluster.wait.aligned;" ::: "memory");

        // ---- phase B: peer-k block (SMEM weights, peer-produced h) ----------
        #pragma unroll
        for (int q = 0; q < 4; q++) {
            __half2 s = hz;
            #pragma unroll
            for (int i = 0; i < 4; i++) {
                int bi = q * 4 + i;
                int k8 = PEER16 + bi;
                uint4 hv = *(const uint4*)(hsp + k8 * 4);
                uint4 wa = w_s[bi * 512 + tid];
                s = __hfma2(*(__half2*)&hv.x, *(__half2*)&wa.x, s);
                s = __hfma2(*(__half2*)&hv.y, *(__half2*)&wa.y, s);
                s = __hfma2(*(__half2*)&hv.z, *(__half2*)&wa.z, s);
                s = __hfma2(*(__half2*)&hv.w, *(__half2*)&wa.w, s);
            }
            float2 f = __half22float2(s);
            acc += f.x + f.y;
        }

        gsh[tid] = tanh_f(acc);
        __syncthreads();

        if (tid < 128) {
            float ig = gsh[tid];
            float fg = gsh[128 + tid];
            float gg = gsh[256 + tid];
            float og = gsh[384 + tid];
            c = c * sig_f(fg) + sig_f(ig) * tanh_f(gg);
            float hn = sig_f(og) * tanh_f(c);
            out[((size_t)(b * HID + half * 128 + tid)) * TT + t] = hn;

            float ho = __shfl_xor_sync(0xffffffffu, hn, 1);
            if (!(tid & 1)) {
                __half2 hp = __floats2half2_rn(hn, ho);
                int k2 = half * 64 + (tid >> 1);
                hs2[(p ^ 1) * 128 + k2] = hp;                 // local copy
                uint32_t laddr = hsAddrBase + (uint32_t)(((p ^ 1) * 128 + k2) * 4);
                uint32_t raddr;
                asm volatile("mapa.shared::cluster.u32 %0, %1, %2;"
                             : "=r"(raddr) : "r"(laddr), "r"(peerRank));
                asm volatile("st.shared::cluster.u32 [%0], %1;"
                             :: "r"(raddr), "r"(*(uint32_t*)&hp));
            }
        }
        __syncthreads();
        asm volatile("barrier.cluster.arrive.aligned;" ::: "memory");

        wx = nx;
    }
    asm volatile("barrier.cluster.wait.aligned;" ::: "memory");

    if (tid < 128)
        out[(size_t)BB * HID * TT + b * HID + half * 128 + tid] = c;
}

// ---------------- launch ------------------------------------------------------
extern "C" void kernel_launch(void* const* d_in, const int* in_sizes, int n_in,
                              void* d_out, int out_size) {
    const float* x   = (const float*)d_in[0];   // (64,256,512)
    const float* h0  = (const float*)d_in[1];   // (64,1,256)
    const float* c0  = (const float*)d_in[2];   // (64,1,256)
    const float* Wih = (const float*)d_in[3];   // (64,256,1024)
    const float* Whh = (const float*)d_in[4];   // (64,256,1024)
    const float* bh  = (const float*)d_in[5];   // (64,1,1024)
    float* out = (float*)d_out;

    cudaFuncSetAttribute(lstm_rec_kernel,
                         cudaFuncAttributeMaxDynamicSharedMemorySize, SMEM_TOTAL_R);

    conv_whh_kernel<<<(BB * 2 * 16 * 512) / 256, 256>>>(Whh);

    dim3 g1(TT / 64, G4 / 64, BB);   // (8, 16, 64)
    wx_gemm_kernel<<<g1, 256>>>(x, Wih, bh);

    lstm_rec_kernel<<<2 * BB, 512, SMEM_TOTAL_R>>>(h0, c0, out);

    (void)in_sizes; (void)n_in; (void)out_size;
}

// round 6
// speedup vs baseline: 1.4659x; 1.4659x over previous
#include <cuda_runtime.h>
#include <cuda_fp16.h>
#include <cstdint>
#include <math.h>

#define BB   64
#define CIN  256
#define HID  256
#define TT   512
#define G4   1024   // 4*HID

// ---------------- scratch (__device__ globals) ------------------------------
__device__ float g_wx[(size_t)TT * BB * G4];      // [t][b][col]  128 MiB
// Recurrence weights fp16: per (b,half): 16 chunks x 512 cols x uint4(8 halves)
__device__ uint4 g_wA[(size_t)BB * 2 * 16 * 512]; // own-k block  (registers)
__device__ uint4 g_wB[(size_t)BB * 2 * 16 * 512]; // peer-k block (SMEM)

// local col lc in [0,512) -> global gate column
__device__ __forceinline__ int gcol(int lc, int half) {
    int g = ((lc >> 7) & 1) | ((lc >> 8) << 1);
    return g * 256 + half * 128 + (lc & 127);
}

// fast activations (MUFU-based, proven rel_err impact ~0 in R5)
__device__ __forceinline__ float tanh_f(float x) {
    float e = __expf(2.0f * x);
    return 1.0f - __fdividef(2.0f, e + 1.0f);
}
__device__ __forceinline__ float sig_f(float x) {
    return __fdividef(1.0f, 1.0f + __expf(-x));
}

// ---------------- conv: W_hh fp32 -> fp16 blobs (proven) --------------------
__global__ __launch_bounds__(256) void conv_whh_kernel(const float* __restrict__ Whh) {
    int t    = blockIdx.x * 256 + threadIdx.x;
    int lc   = t & 511;
    int k8   = (t >> 9) & 15;
    int half = (t >> 13) & 1;
    int b    = t >> 14;
    int col  = gcol(lc, half);
    {
        int kg0 = half * 128 + k8 * 8;
        const float* s = Whh + ((size_t)b * HID + kg0) * G4 + col;
        __half hx[8];
        #pragma unroll
        for (int i = 0; i < 8; i++) hx[i] = __float2half(s[(size_t)i * G4]);
        g_wA[t] = *(uint4*)hx;
    }
    {
        int kg0 = (1 - half) * 128 + k8 * 8;
        const float* s = Whh + ((size_t)b * HID + kg0) * G4 + col;
        __half hx[8];
        #pragma unroll
        for (int i = 0; i < 8; i++) hx[i] = __float2half(s[(size_t)i * G4]);
        g_wB[t] = *(uint4*)hx;
    }
}

// ---------------- phase 1: single-kernel HMMA GEMM --------------------------
// g_wx[t][b][col] = sum_k x[b][k][t] * W_ih[b][k][col] + b_h[b][col]
// A(t,k) = x[k][t], B(k,n) = W_ih[k][n].  Staged in smem as As[t][k], Bs[n][k].
__device__ __forceinline__ void mma16816(float* d, const uint32_t* a, const uint32_t* bf) {
    asm volatile(
        "mma.sync.aligned.m16n8k16.row.col.f32.f16.f16.f32 "
        "{%0,%1,%2,%3}, {%4,%5,%6,%7}, {%8,%9}, {%0,%1,%2,%3};"
        : "+f"(d[0]), "+f"(d[1]), "+f"(d[2]), "+f"(d[3])
        : "r"(a[0]), "r"(a[1]), "r"(a[2]), "r"(a[3]), "r"(bf[0]), "r"(bf[1]));
}

#define LDA 40   // 32 k + 8 pad halves: fragment LDS is bank-conflict-free

__global__ __launch_bounds__(256) void wx_hmma_kernel(
    const float* __restrict__ x,     // [B][CIN][T]
    const float* __restrict__ Wih,   // [B][CIN][4H]
    const float* __restrict__ bh)    // [B][1][4H]
{
    __shared__ __half As[128 * LDA];   // [t_local][k_local]
    __shared__ __half Bs[128 * LDA];   // [n_local][k_local]

    const int tid  = threadIdx.x;
    const int m0   = blockIdx.x * 128;     // t tile
    const int n0   = blockIdx.y * 128;     // col tile
    const int b    = blockIdx.z;
    const int wid  = tid >> 5, lane = tid & 31;
    const int wm   = (wid & 1) * 64, wn = (wid >> 1) * 32;
    const int g    = lane >> 2, tig = lane & 3;

    float acc[4][4][4];
    #pragma unroll
    for (int i = 0; i < 4; i++)
        #pragma unroll
        for (int j = 0; j < 4; j++)
            #pragma unroll
            for (int r = 0; r < 4; r++) acc[i][j][r] = 0.0f;

    const float* xb = x   + (size_t)b * CIN * TT + m0;
    const float* wb = Wih + (size_t)b * CIN * G4 + n0;

    #pragma unroll 1
    for (int kb = 0; kb < CIN; kb += 32) {
        // stage x tile: 32 k x 128 t, transpose+convert at store
        #pragma unroll
        for (int i = 0; i < 4; i++) {
            int idx = tid + i * 256;            // 0..1023
            int kl = idx >> 5, tq = idx & 31;   // k_local, t-quad
            float4 v = *(const float4*)(xb + (size_t)(kb + kl) * TT + tq * 4);
            __half* d = As + (tq * 4) * LDA + kl;
            d[0]       = __float2half_rn(v.x);
            d[LDA]     = __float2half_rn(v.y);
            d[2 * LDA] = __float2half_rn(v.z);
            d[3 * LDA] = __float2half_rn(v.w);
        }
        // stage W tile: 32 k x 128 n
        #pragma unroll
        for (int i = 0; i < 4; i++) {
            int idx = tid + i * 256;
            int kl = idx >> 5, nq = idx & 31;
            float4 v = *(const float4*)(wb + (size_t)(kb + kl) * G4 + nq * 4);
            __half* d = Bs + (nq * 4) * LDA + kl;
            d[0]       = __float2half_rn(v.x);
            d[LDA]     = __float2half_rn(v.y);
            d[2 * LDA] = __float2half_rn(v.z);
            d[3 * LDA] = __float2half_rn(v.w);
        }
        __syncthreads();

        #pragma unroll
        for (int ks = 0; ks < 2; ks++) {
            uint32_t a[4][4], bf[4][2];
            #pragma unroll
            for (int mf = 0; mf < 4; mf++) {
                const __half* base = As + (wm + mf * 16 + g) * LDA + ks * 16 + tig * 2;
                a[mf][0] = *(const uint32_t*)(base);             // (g,   2tig)
                a[mf][1] = *(const uint32_t*)(base + 8 * LDA);   // (g+8, 2tig)
                a[mf][2] = *(const uint32_t*)(base + 8);         // (g,   2tig+8)
                a[mf][3] = *(const uint32_t*)(base + 8 * LDA + 8);
            }
            #pragma unroll
            for (int nf = 0; nf < 4; nf++) {
                const __half* base = Bs + (wn + nf * 8 + g) * LDA + ks * 16 + tig * 2;
                bf[nf][0] = *(const uint32_t*)(base);            // (2tig, g)
                bf[nf][1] = *(const uint32_t*)(base + 8);        // (2tig+8, g)
            }
            #pragma unroll
            for (int mf = 0; mf < 4; mf++)
                #pragma unroll
                for (int nf = 0; nf < 4; nf++)
                    mma16816(acc[mf][nf], a[mf], bf[nf]);
        }
        __syncthreads();
    }

    // epilogue: add bias, write g_wx[t][b][col]
    #pragma unroll
    for (int nf = 0; nf < 4; nf++) {
        int col = n0 + wn + nf * 8 + tig * 2;
        float2 bias = *(const float2*)(bh + (size_t)b * G4 + col);
        #pragma unroll
        for (int mf = 0; mf < 4; mf++) {
            int t0 = m0 + wm + mf * 16 + g;
            float2 v0 = { acc[mf][nf][0] + bias.x, acc[mf][nf][1] + bias.y };
            float2 v1 = { acc[mf][nf][2] + bias.x, acc[mf][nf][3] + bias.y };
            *(float2*)(g_wx + ((size_t)t0 * BB + b) * G4 + col) = v0;
            *(float2*)(g_wx + ((size_t)(t0 + 8) * BB + b) * G4 + col) = v1;
        }
    }
}

// ---------------- phase 2: recurrence (R3-proven structure) -----------------
#define SMEM_W_BYTES  (16 * 512 * 16)                 // 131072
#define SMEM_HS_OFF   SMEM_W_BYTES
#define SMEM_GS_OFF   (SMEM_HS_OFF + 2 * 128 * 4)
#define SMEM_TOTAL_R  (SMEM_GS_OFF + 512 * 4)         // 134144 B

__global__ void __cluster_dims__(2, 1, 1) __launch_bounds__(256, 1)
lstm_rec_kernel(const float* __restrict__ h0,
                const float* __restrict__ c0,
                float* __restrict__ out)
{
    extern __shared__ char smem[];
    uint4*   w_s  = (uint4*)smem;
    __half2* hs2  = (__half2*)(smem + SMEM_HS_OFF);
    float*   gsh  = (float*)(smem + SMEM_GS_OFF);

    const int tid    = threadIdx.x;
    const int b      = blockIdx.x >> 1;
    const int half   = blockIdx.x & 1;
    const int HALF16 = half * 16;
    const int PEER16 = 16 - HALF16;

    uint4 wregA[16], wregB[16];
    const uint4* gwa = g_wA + ((size_t)(b * 2 + half) << 13);
    #pragma unroll
    for (int a = 0; a < 16; a++) {
        wregA[a] = gwa[a * 512 + tid];
        wregB[a] = gwa[a * 512 + tid + 256];
    }
    const uint4* gwb = g_wB + ((size_t)(b * 2 + half) << 13);
    #pragma unroll
    for (int i = 0; i < 32; i++) w_s[i * 256 + tid] = gwb[i * 256 + tid];

    float c = 0.0f;
    if (tid < 128) {
        c = c0[b * HID + half * 128 + tid];
        hs2[tid] = __floats2half2_rn(h0[b * HID + 2 * tid],
                                     h0[b * HID + 2 * tid + 1]);
    }
    __syncthreads();
    asm volatile("barrier.cluster.arrive.aligned;\n\t"
                 "barrier.cluster.wait.aligned;" ::: "memory");

    const uint32_t hsAddrBase = (uint32_t)__cvta_generic_to_shared(hs2);
    const uint32_t peerRank   = (uint32_t)(half ^ 1);

    const int colA = gcol(tid, half);
    const float* wxA_ptr = g_wx + (size_t)b * G4 + colA;
    const float* wxB_ptr = wxA_ptr + 512;

    float wxA = __ldg(wxA_ptr);
    float wxB = __ldg(wxB_ptr);
    const __half2 hz = __float2half2_rn(0.0f);

    #pragma unroll 1
    for (int t = 0; t < TT; t++) {
        const int p = t & 1;

        float nxA = wxA, nxB = wxB;
        if (t + 1 < TT) {
            size_t off = (size_t)(t + 1) * (BB * G4);
            nxA = __ldg(wxA_ptr + off);
            nxB = __ldg(wxB_ptr + off);
        }

        float accA = wxA, accB = wxB;
        const __half2* hsp = hs2 + p * 128;

        // ---- phase A: own-k block (register weights) ----
        #pragma unroll
        for (int q = 0; q < 4; q++) {
            __half2 sA = hz, sB = hz;
            #pragma unroll
            for (int i = 0; i < 4; i++) {
                int a  = q * 4 + i;
                int k8 = HALF16 + a;
                uint4 hv = *(const uint4*)(hsp + k8 * 4);
                __half2 h01 = *(__half2*)&hv.x, h23 = *(__half2*)&hv.y;
                __half2 h45 = *(__half2*)&hv.z, h67 = *(__half2*)&hv.w;
                uint4 wa = wregA[a], wb = wregB[a];
                sA = __hfma2(h01, *(__half2*)&wa.x, sA);
                sA = __hfma2(h23, *(__half2*)&wa.y, sA);
                sA = __hfma2(h45, *(__half2*)&wa.z, sA);
                sA = __hfma2(h67, *(__half2*)&wa.w, sA);
                sB = __hfma2(h01, *(__half2*)&wb.x, sB);
                sB = __hfma2(h23, *(__half2*)&wb.y, sB);
                sB = __hfma2(h45, *(__half2*)&wb.z, sB);
                sB = __hfma2(h67, *(__half2*)&wb.w, sB);
            }
            float2 fa = __half22float2(sA); accA += fa.x + fa.y;
            float2 fb = __half22float2(sB); accB += fb.x + fb.y;
        }

        if (t) asm volatile("barrier.cluster.wait.aligned;" ::: "memory");

        // ---- phase B: peer-k block (SMEM weights) ----
        #pragma unroll
        for (int q = 0; q < 4; q++) {
            __half2 sA = hz, sB = hz;
            #pragma unroll
            for (int i = 0; i < 4; i++) {
                int bi = q * 4 + i;
                int k8 = PEER16 + bi;
                uint4 hv = *(const uint4*)(hsp + k8 * 4);
                __half2 h01 = *(__half2*)&hv.x, h23 = *(__half2*)&hv.y;
                __half2 h45 = *(__half2*)&hv.z, h67 = *(__half2*)&hv.w;
                uint4 wa = w_s[bi * 512 + tid];
                uint4 wb = w_s[bi * 512 + tid + 256];
                sA = __hfma2(h01, *(__half2*)&wa.x, sA);
                sA = __hfma2(h23, *(__half2*)&wa.y, sA);
                sA = __hfma2(h45, *(__half2*)&wa.z, sA);
                sA = __hfma2(h67, *(__half2*)&wa.w, sA);
                sB = __hfma2(h01, *(__half2*)&wb.x, sB);
                sB = __hfma2(h23, *(__half2*)&wb.y, sB);
                sB = __hfma2(h45, *(__half2*)&wb.z, sB);
                sB = __hfma2(h67, *(__half2*)&wb.w, sB);
            }
            float2 fa = __half22float2(sA); accA += fa.x + fa.y;
            float2 fb = __half22float2(sB); accB += fb.x + fb.y;
        }

        gsh[tid]       = tanh_f(accA);
        gsh[tid + 256] = tanh_f(accB);
        __syncthreads();

        if (tid < 128) {
            float ig = gsh[tid];
            float fg = gsh[128 + tid];
            float gg = gsh[256 + tid];
            float og = gsh[384 + tid];
            c = c * sig_f(fg) + sig_f(ig) * tanh_f(gg);
            float hn = sig_f(og) * tanh_f(c);
            out[((size_t)(b * HID + half * 128 + tid)) * TT + t] = hn;

            float ho = __shfl_xor_sync(0xffffffffu, hn, 1);
            if (!(tid & 1)) {
                __half2 hp = __floats2half2_rn(hn, ho);
                int k2 = half * 64 + (tid >> 1);
                hs2[(p ^ 1) * 128 + k2] = hp;
                uint32_t laddr = hsAddrBase + (uint32_t)(((p ^ 1) * 128 + k2) * 4);
                uint32_t raddr;
                asm volatile("mapa.shared::cluster.u32 %0, %1, %2;"
                             : "=r"(raddr) : "r"(laddr), "r"(peerRank));
                asm volatile("st.shared::cluster.u32 [%0], %1;"
                             :: "r"(raddr), "r"(*(uint32_t*)&hp));
            }
        }
        __syncthreads();
        asm volatile("barrier.cluster.arrive.aligned;" ::: "memory");

        wxA = nxA; wxB = nxB;
    }
    asm volatile("barrier.cluster.wait.aligned;" ::: "memory");

    if (tid < 128)
        out[(size_t)BB * HID * TT + b * HID + half * 128 + tid] = c;
}

// ---------------- launch ------------------------------------------------------
extern "C" void kernel_launch(void* const* d_in, const int* in_sizes, int n_in,
                              void* d_out, int out_size) {
    const float* x   = (const float*)d_in[0];   // (64,256,512)
    const float* h0  = (const float*)d_in[1];   // (64,1,256)
    const float* c0  = (const float*)d_in[2];   // (64,1,256)
    const float* Wih = (const float*)d_in[3];   // (64,256,1024)
    const float* Whh = (const float*)d_in[4];   // (64,256,1024)
    const float* bh  = (const float*)d_in[5];   // (64,1,1024)
    float* out = (float*)d_out;

    cudaFuncSetAttribute(lstm_rec_kernel,
                         cudaFuncAttributeMaxDynamicSharedMemorySize, SMEM_TOTAL_R);

    conv_whh_kernel<<<(BB * 2 * 16 * 512) / 256, 256>>>(Whh);

    wx_hmma_kernel<<<dim3(TT / 128, G4 / 128, BB), 256>>>(x, Wih, bh);

    lstm_rec_kernel<<<2 * BB, 256, SMEM_TOTAL_R>>>(h0, c0, out);

    (void)in_sizes; (void)n_in; (void)out_size;
}

// round 7
// speedup vs baseline: 1.4941x; 1.0192x over previous
#include <cuda_runtime.h>
#include <cuda_fp16.h>
#include <cstdint>
#include <math.h>

#define BB   64
#define CIN  256
#define HID  256
#define TT   512
#define G4   1024   // 4*HID

// ---------------- scratch (__device__ globals) ------------------------------
__device__ float g_wx[(size_t)TT * BB * G4];      // [t][b][col]  128 MiB
// Recurrence weights fp16: per (b,half): 16 chunks x 512 cols x uint4(8 halves)
__device__ uint4 g_wA[(size_t)BB * 2 * 16 * 512]; // own-k block
__device__ uint4 g_wB[(size_t)BB * 2 * 16 * 512]; // peer-k block

// column slot lc in [0,512) -> global gate column.
// slot th=lc&255 is the owning thread; sel=lc>>8 its 1st/2nd column.
// tid<128  -> gates (i=0, g=2) of unit tid
// tid>=128 -> gates (f=1, o=3) of unit tid-128
__device__ __forceinline__ int gcol(int lc, int half) {
    int th  = lc & 255;
    int sel = lc >> 8;
    int g   = (th < 128) ? (sel * 2) : (sel * 2 + 1);
    int j   = th & 127;
    return g * 256 + half * 128 + j;
}

// fast activations (MUFU-based, accuracy-proven in R5/R6)
__device__ __forceinline__ float tanh_f(float x) {
    float e = __expf(2.0f * x);
    return 1.0f - __fdividef(2.0f, e + 1.0f);
}
__device__ __forceinline__ float sig_f(float x) {
    return __fdividef(1.0f, 1.0f + __expf(-x));
}

// ---------------- conv: W_hh fp32 -> fp16 blobs ------------------------------
__global__ __launch_bounds__(256) void conv_whh_kernel(const float* __restrict__ Whh) {
    int t    = blockIdx.x * 256 + threadIdx.x;
    int lc   = t & 511;
    int k8   = (t >> 9) & 15;
    int half = (t >> 13) & 1;
    int b    = t >> 14;
    int col  = gcol(lc, half);
    {
        int kg0 = half * 128 + k8 * 8;
        const float* s = Whh + ((size_t)b * HID + kg0) * G4 + col;
        __half hx[8];
        #pragma unroll
        for (int i = 0; i < 8; i++) hx[i] = __float2half(s[(size_t)i * G4]);
        g_wA[t] = *(uint4*)hx;
    }
    {
        int kg0 = (1 - half) * 128 + k8 * 8;
        const float* s = Whh + ((size_t)b * HID + kg0) * G4 + col;
        __half hx[8];
        #pragma unroll
        for (int i = 0; i < 8; i++) hx[i] = __float2half(s[(size_t)i * G4]);
        g_wB[t] = *(uint4*)hx;
    }
}

// ---------------- phase 1: single-kernel HMMA GEMM (R6-proven) --------------
__device__ __forceinline__ void mma16816(float* d, const uint32_t* a, const uint32_t* bf) {
    asm volatile(
        "mma.sync.aligned.m16n8k16.row.col.f32.f16.f16.f32 "
        "{%0,%1,%2,%3}, {%4,%5,%6,%7}, {%8,%9}, {%0,%1,%2,%3};"
        : "+f"(d[0]), "+f"(d[1]), "+f"(d[2]), "+f"(d[3])
        : "r"(a[0]), "r"(a[1]), "r"(a[2]), "r"(a[3]), "r"(bf[0]), "r"(bf[1]));
}

#define LDA 40   // 32 k + 8 pad halves

__global__ __launch_bounds__(256) void wx_hmma_kernel(
    const float* __restrict__ x,     // [B][CIN][T]
    const float* __restrict__ Wih,   // [B][CIN][4H]
    const float* __restrict__ bh)    // [B][1][4H]
{
    __shared__ __half As[128 * LDA];
    __shared__ __half Bs[128 * LDA];

    const int tid  = threadIdx.x;
    const int m0   = blockIdx.x * 128;
    const int n0   = blockIdx.y * 128;
    const int b    = blockIdx.z;
    const int wid  = tid >> 5, lane = tid & 31;
    const int wm   = (wid & 1) * 64, wn = (wid >> 1) * 32;
    const int g    = lane >> 2, tig = lane & 3;

    float acc[4][4][4];
    #pragma unroll
    for (int i = 0; i < 4; i++)
        #pragma unroll
        for (int j = 0; j < 4; j++)
            #pragma unroll
            for (int r = 0; r < 4; r++) acc[i][j][r] = 0.0f;

    const float* xb = x   + (size_t)b * CIN * TT + m0;
    const float* wb = Wih + (size_t)b * CIN * G4 + n0;

    #pragma unroll 1
    for (int kb = 0; kb < CIN; kb += 32) {
        #pragma unroll
        for (int i = 0; i < 4; i++) {
            int idx = tid + i * 256;
            int kl = idx >> 5, tq = idx & 31;
            float4 v = *(const float4*)(xb + (size_t)(kb + kl) * TT + tq * 4);
            __half* d = As + (tq * 4) * LDA + kl;
            d[0]       = __float2half_rn(v.x);
            d[LDA]     = __float2half_rn(v.y);
            d[2 * LDA] = __float2half_rn(v.z);
            d[3 * LDA] = __float2half_rn(v.w);
        }
        #pragma unroll
        for (int i = 0; i < 4; i++) {
            int idx = tid + i * 256;
            int kl = idx >> 5, nq = idx & 31;
            float4 v = *(const float4*)(wb + (size_t)(kb + kl) * G4 + nq * 4);
            __half* d = Bs + (nq * 4) * LDA + kl;
            d[0]       = __float2half_rn(v.x);
            d[LDA]     = __float2half_rn(v.y);
            d[2 * LDA] = __float2half_rn(v.z);
            d[3 * LDA] = __float2half_rn(v.w);
        }
        __syncthreads();

        #pragma unroll
        for (int ks = 0; ks < 2; ks++) {
            uint32_t a[4][4], bf[4][2];
            #pragma unroll
            for (int mf = 0; mf < 4; mf++) {
                const __half* base = As + (wm + mf * 16 + g) * LDA + ks * 16 + tig * 2;
                a[mf][0] = *(const uint32_t*)(base);
                a[mf][1] = *(const uint32_t*)(base + 8 * LDA);
                a[mf][2] = *(const uint32_t*)(base + 8);
                a[mf][3] = *(const uint32_t*)(base + 8 * LDA + 8);
            }
            #pragma unroll
            for (int nf = 0; nf < 4; nf++) {
                const __half* base = Bs + (wn + nf * 8 + g) * LDA + ks * 16 + tig * 2;
                bf[nf][0] = *(const uint32_t*)(base);
                bf[nf][1] = *(const uint32_t*)(base + 8);
            }
            #pragma unroll
            for (int mf = 0; mf < 4; mf++)
                #pragma unroll
                for (int nf = 0; nf < 4; nf++)
                    mma16816(acc[mf][nf], a[mf], bf[nf]);
        }
        __syncthreads();
    }

    #pragma unroll
    for (int nf = 0; nf < 4; nf++) {
        int col = n0 + wn + nf * 8 + tig * 2;
        float2 bias = *(const float2*)(bh + (size_t)b * G4 + col);
        #pragma unroll
        for (int mf = 0; mf < 4; mf++) {
            int t0 = m0 + wm + mf * 16 + g;
            float2 v0 = { acc[mf][nf][0] + bias.x, acc[mf][nf][1] + bias.y };
            float2 v1 = { acc[mf][nf][2] + bias.x, acc[mf][nf][3] + bias.y };
            *(float2*)(g_wx + ((size_t)t0 * BB + b) * G4 + col) = v0;
            *(float2*)(g_wx + ((size_t)(t0 + 8) * BB + b) * G4 + col) = v1;
        }
    }
}

// ---------------- phase 2: recurrence ---------------------------------------
// peer chunks 8..15 in SMEM; chunks 0..7 register-resident.
#define SMEM_W_BYTES  (8 * 512 * 16)                  // 65536
#define SMEM_HS_OFF   SMEM_W_BYTES
#define SMEM_GS_OFF   (SMEM_HS_OFF + 2 * 128 * 4)
#define SMEM_TOTAL_R  (SMEM_GS_OFF + 128 * 4)         // 67072 B

__global__ void __cluster_dims__(2, 1, 1) __launch_bounds__(256, 1)
lstm_rec_kernel(const float* __restrict__ h0,
                const float* __restrict__ c0,
                float* __restrict__ out)
{
    extern __shared__ char smem[];
    uint4*   w_s  = (uint4*)smem;                     // peer chunks 8..15
    __half2* hs2  = (__half2*)(smem + SMEM_HS_OFF);
    float*   gsh  = (float*)(smem + SMEM_GS_OFF);     // u exchange (128 floats)

    const int tid    = threadIdx.x;
    const int b      = blockIdx.x >> 1;
    const int half   = blockIdx.x & 1;
    const int HALF16 = half * 16;
    const int PEER16 = 16 - HALF16;
    const bool hi    = (tid >= 128);
    const int  j     = tid & 127;

    // --- weight residency: own 16 chunks + peer 8 chunks in regs ------------
    uint4 wregA[16], wregB[16], wregPA[8], wregPB[8];
    const uint4* gwa = g_wA + ((size_t)(b * 2 + half) << 13);
    #pragma unroll
    for (int a = 0; a < 16; a++) {
        wregA[a] = gwa[a * 512 + tid];
        wregB[a] = gwa[a * 512 + tid + 256];
    }
    const uint4* gwb = g_wB + ((size_t)(b * 2 + half) << 13);
    #pragma unroll
    for (int a = 0; a < 8; a++) {
        wregPA[a] = gwb[a * 512 + tid];
        wregPB[a] = gwb[a * 512 + tid + 256];
    }
    #pragma unroll
    for (int a = 8; a < 16; a++) {
        w_s[(a - 8) * 512 + tid]       = gwb[a * 512 + tid];
        w_s[(a - 8) * 512 + tid + 256] = gwb[a * 512 + tid + 256];
    }

    // --- init state ---
    float c = 0.0f;
    if (hi) c = c0[b * HID + half * 128 + j];
    if (tid < 128)
        hs2[tid] = __floats2half2_rn(h0[b * HID + 2 * tid],
                                     h0[b * HID + 2 * tid + 1]);
    __syncthreads();
    asm volatile("barrier.cluster.arrive.aligned;\n\t"
                 "barrier.cluster.wait.aligned;" ::: "memory");

    const uint32_t hsAddrBase = (uint32_t)__cvta_generic_to_shared(hs2);
    const uint32_t peerRank   = (uint32_t)(half ^ 1);

    const int colA = gcol(tid, half);
    const float* wxA_ptr = g_wx + (size_t)b * G4 + colA;
    const float* wxB_ptr = wxA_ptr + 512;    // second gate = first + 2*256

    float wxA = __ldg(wxA_ptr);
    float wxB = __ldg(wxB_ptr);
    const __half2 hz = __float2half2_rn(0.0f);

    #pragma unroll 1
    for (int t = 0; t < TT; t++) {
        const int p = t & 1;

        float nxA = wxA, nxB = wxB;
        if (t + 1 < TT) {
            size_t off = (size_t)(t + 1) * (BB * G4);
            nxA = __ldg(wxA_ptr + off);
            nxB = __ldg(wxB_ptr + off);
        }

        float accA = wxA, accB = wxB;
        const __half2* hsp = hs2 + p * 128;

        // ---- phase A: own-k block (register weights) ----
        #pragma unroll
        for (int q = 0; q < 4; q++) {
            __half2 sA = hz, sB = hz;
            #pragma unroll
            for (int i = 0; i < 4; i++) {
                int a  = q * 4 + i;
                int k8 = HALF16 + a;
                uint4 hv = *(const uint4*)(hsp + k8 * 4);
                __half2 h01 = *(__half2*)&hv.x, h23 = *(__half2*)&hv.y;
                __half2 h45 = *(__half2*)&hv.z, h67 = *(__half2*)&hv.w;
                uint4 wa = wregA[a], wb = wregB[a];
                sA = __hfma2(h01, *(__half2*)&wa.x, sA);
                sA = __hfma2(h23, *(__half2*)&wa.y, sA);
                sA = __hfma2(h45, *(__half2*)&wa.z, sA);
                sA = __hfma2(h67, *(__half2*)&wa.w, sA);
                sB = __hfma2(h01, *(__half2*)&wb.x, sB);
                sB = __hfma2(h23, *(__half2*)&wb.y, sB);
                sB = __hfma2(h45, *(__half2*)&wb.z, sB);
                sB = __hfma2(h67, *(__half2*)&wb.w, sB);
            }
            float2 fa = __half22float2(sA); accA += fa.x + fa.y;
            float2 fb = __half22float2(sB); accB += fb.x + fb.y;
        }

        if (t) asm volatile("barrier.cluster.wait.aligned;" ::: "memory");

        // ---- phase B: peer-k block (8 reg chunks + 8 SMEM chunks) ----
        #pragma unroll
        for (int q = 0; q < 4; q++) {
            __half2 sA = hz, sB = hz;
            #pragma unroll
            for (int i = 0; i < 4; i++) {
                int bi = q * 4 + i;
                int k8 = PEER16 + bi;
                uint4 hv = *(const uint4*)(hsp + k8 * 4);
                __half2 h01 = *(__half2*)&hv.x, h23 = *(__half2*)&hv.y;
                __half2 h45 = *(__half2*)&hv.z, h67 = *(__half2*)&hv.w;
                uint4 wa, wb;
                if (bi < 8) { wa = wregPA[bi]; wb = wregPB[bi]; }
                else {
                    wa = w_s[(bi - 8) * 512 + tid];
                    wb = w_s[(bi - 8) * 512 + tid + 256];
                }
                sA = __hfma2(h01, *(__half2*)&wa.x, sA);
                sA = __hfma2(h23, *(__half2*)&wa.y, sA);
                sA = __hfma2(h45, *(__half2*)&wa.z, sA);
                sA = __hfma2(h67, *(__half2*)&wa.w, sA);
                sB = __hfma2(h01, *(__half2*)&wb.x, sB);
                sB = __hfma2(h23, *(__half2*)&wb.y, sB);
                sB = __hfma2(h45, *(__half2*)&wb.z, sB);
                sB = __hfma2(h67, *(__half2*)&wb.w, sB);
            }
            float2 fa = __half22float2(sA); accA += fa.x + fa.y;
            float2 fb = __half22float2(sB); accB += fb.x + fb.y;
        }

        // ---- activations, split by role ----
        float ga = tanh_f(accA);   // lo: tanh(i-gate)   hi: tanh(f-gate)
        float gb = tanh_f(accB);   // lo: tanh(g-gate)   hi: tanh(o-gate)

        if (!hi) gsh[j] = sig_f(ga) * tanh_f(gb);   // u = sigma(i)*tanh(g)
        __syncthreads();

        if (hi) {
            c = c * sig_f(ga) + gsh[j];
            float hn = sig_f(gb) * tanh_f(c);
            out[((size_t)(b * HID + half * 128 + j)) * TT + t] = hn;

            float ho = __shfl_xor_sync(0xffffffffu, hn, 1);
            if (!(j & 1)) {
                __half2 hp = __floats2half2_rn(hn, ho);
                int k2 = half * 64 + (j >> 1);
                hs2[(p ^ 1) * 128 + k2] = hp;
                uint32_t laddr = hsAddrBase + (uint32_t)(((p ^ 1) * 128 + k2) * 4);
                uint32_t raddr;
                asm volatile("mapa.shared::cluster.u32 %0, %1, %2;"
                             : "=r"(raddr) : "r"(laddr), "r"(peerRank));
                asm volatile("st.shared::cluster.u32 [%0], %1;"
                             :: "r"(raddr), "r"(*(uint32_t*)&hp));
            }
        }
        __syncthreads();
        asm volatile("barrier.cluster.arrive.aligned;" ::: "memory");

        wxA = nxA; wxB = nxB;
    }
    asm volatile("barrier.cluster.wait.aligned;" ::: "memory");

    if (hi)
        out[(size_t)BB * HID * TT + b * HID + half * 128 + j] = c;
}

// ---------------- launch ------------------------------------------------------
extern "C" void kernel_launch(void* const* d_in, const int* in_sizes, int n_in,
                              void* d_out, int out_size) {
    const float* x   = (const float*)d_in[0];
    const float* h0  = (const float*)d_in[1];
    const float* c0  = (const float*)d_in[2];
    const float* Wih = (const float*)d_in[3];
    const float* Whh = (const float*)d_in[4];
    const float* bh  = (const float*)d_in[5];
    float* out = (float*)d_out;

    cudaFuncSetAttribute(lstm_rec_kernel,
                         cudaFuncAttributeMaxDynamicSharedMemorySize, SMEM_TOTAL_R);

    conv_whh_kernel<<<(BB * 2 * 16 * 512) / 256, 256>>>(Whh);

    wx_hmma_kernel<<<dim3(TT / 128, G4 / 128, BB), 256>>>(x, Wih, bh);

    lstm_rec_kernel<<<2 * BB, 256, SMEM_TOTAL_R>>>(h0, c0, out);

    (void)in_sizes; (void)n_in; (void)out_size;
}